// round 1
// baseline (speedup 1.0000x reference)
#include <cuda_runtime.h>
#include <cuda_bf16.h>

// 2-layer LSTM (H=32) + final LayerNorm, B=4096, T=512, D=6.
// Strategy: warp processes 2 batch elements; lane j owns hidden unit j.
// Weights in shared, permuted so lane j's i/f/g/o weights for unit j are a
// contiguous float4 -> one conflict-free LDS.128 per k, no gate transpose.
// h vectors broadcast from per-warp shared buffers. Sequential over T.

#define T_STEPS 512
#define D_IN 6
#define HID 32
#define GATES 128          // 4*HID
#define BATCH 4096
#define WARPS_PER_CTA 14
#define CTA_THREADS (WARPS_PER_CTA * 32)
#define NUM_CTAS 147       // 147*14 = 2058 warp tasks >= 2048 (2 batches/warp)

// shared floats: Wih0(6*128) + Whh0(32*128) + Wih1(32*128) + Whh1(32*128)
//              + b0(128) + b1(128) + hbuf(14 warps * 128)
#define SMEM_FLOATS (768 + 4096*3 + 256 + WARPS_PER_CTA*128)
#define SMEM_BYTES (SMEM_FLOATS * 4)

__device__ __forceinline__ float sigf(float x) {
    return __fdividef(1.0f, 1.0f + __expf(-x));
}
__device__ __forceinline__ float tanh_(float x) {
    // 2*sigmoid(2x)-1 ; saturates correctly at +-inf, no NaN.
    return __fdividef(2.0f, 1.0f + __expf(-2.0f * x)) - 1.0f;
}

__global__ __launch_bounds__(CTA_THREADS, 1)
void lstm_enc_kernel(const float* __restrict__ x,
                     const float* __restrict__ W_ih0,
                     const float* __restrict__ W_hh0,
                     const float* __restrict__ b_ih0,
                     const float* __restrict__ b_hh0,
                     const float* __restrict__ W_ih1,
                     const float* __restrict__ W_hh1,
                     const float* __restrict__ b_ih1,
                     const float* __restrict__ b_hh1,
                     const float* __restrict__ ln_gamma,
                     const float* __restrict__ ln_beta,
                     float* __restrict__ out)
{
    extern __shared__ float smem[];
    float* sWih0 = smem;                 // [6][128]  perm: [k][4*j+gate]
    float* sWhh0 = sWih0 + 768;          // [32][128]
    float* sWih1 = sWhh0 + 4096;         // [32][128]
    float* sWhh1 = sWih1 + 4096;         // [32][128]
    float* sB0   = sWhh1 + 4096;         // [128] combined b_ih0+b_hh0 (perm)
    float* sB1   = sB0 + 128;            // [128]
    float* hbuf  = sB1 + 128;            // per warp: h0a[32] h0b[32] h1a[32] h1b[32]

    const int tid = threadIdx.x;

    // ---- load weights into shared with (k, 4*j+gate) permutation ----
    for (int i = tid; i < 6 * 128; i += CTA_THREADS) {
        int k = i >> 7, c = i & 127;
        int j = c >> 2, g = c & 3;
        sWih0[i] = W_ih0[(g * 32 + j) * 6 + k];
    }
    for (int i = tid; i < 32 * 128; i += CTA_THREADS) {
        int k = i >> 7, c = i & 127;
        int j = c >> 2, g = c & 3;
        int row = (g * 32 + j) * 32 + k;
        sWhh0[i] = W_hh0[row];
        sWih1[i] = W_ih1[row];
        sWhh1[i] = W_hh1[row];
    }
    for (int c = tid; c < 128; c += CTA_THREADS) {
        int j = c >> 2, g = c & 3;
        int r = g * 32 + j;
        sB0[c] = b_ih0[r] + b_hh0[r];
        sB1[c] = b_ih1[r] + b_hh1[r];
    }
    __syncthreads();

    const int wid = tid >> 5;
    const int j = tid & 31;
    const int task = blockIdx.x * WARPS_PER_CTA + wid;
    if (task * 2 >= BATCH) return;

    const int ba = task * 2;
    const int bb = ba + 1;

    float* h0a = hbuf + wid * 128;
    float* h0b = h0a + 32;
    float* h1a = h0b + 32;
    float* h1b = h1a + 32;

    h0a[j] = 0.0f; h0b[j] = 0.0f; h1a[j] = 0.0f; h1b[j] = 0.0f;
    __syncwarp();

    const float4 b0q = *(const float4*)&sB0[4 * j];
    const float4 b1q = *(const float4*)&sB1[4 * j];

    float c0a = 0.f, c0b = 0.f, c1a = 0.f, c1b = 0.f;
    float h1a_last = 0.f, h1b_last = 0.f;

    const float* xpa = x + (size_t)ba * T_STEPS * D_IN;
    const float* xpb = x + (size_t)bb * T_STEPS * D_IN;

    // current-timestep x in registers (prefetched)
    float xca[6], xcb[6];
    {
        float2 a0 = *(const float2*)(xpa + 0);
        float2 a1 = *(const float2*)(xpa + 2);
        float2 a2 = *(const float2*)(xpa + 4);
        float2 bb0 = *(const float2*)(xpb + 0);
        float2 bb1 = *(const float2*)(xpb + 2);
        float2 bb2 = *(const float2*)(xpb + 4);
        xca[0]=a0.x; xca[1]=a0.y; xca[2]=a1.x; xca[3]=a1.y; xca[4]=a2.x; xca[5]=a2.y;
        xcb[0]=bb0.x; xcb[1]=bb0.y; xcb[2]=bb1.x; xcb[3]=bb1.y; xcb[4]=bb2.x; xcb[5]=bb2.y;
    }

    for (int t = 0; t < T_STEPS; t++) {
        // prefetch next timestep's x
        int tn = (t + 1 < T_STEPS) ? (t + 1) : t;
        const float* pa = xpa + tn * D_IN;
        const float* pb = xpb + tn * D_IN;
        float2 na0 = *(const float2*)(pa + 0);
        float2 na1 = *(const float2*)(pa + 2);
        float2 na2 = *(const float2*)(pa + 4);
        float2 nb0 = *(const float2*)(pb + 0);
        float2 nb1 = *(const float2*)(pb + 2);
        float2 nb2 = *(const float2*)(pb + 4);

        // ================= Layer 0 =================
        float4 A = b0q, Bv = b0q;
        #pragma unroll
        for (int d = 0; d < 6; d++) {
            float4 w = *(const float4*)&sWih0[d * 128 + 4 * j];
            float va = xca[d], vb = xcb[d];
            A.x  += w.x * va; A.y  += w.y * va; A.z  += w.z * va; A.w  += w.w * va;
            Bv.x += w.x * vb; Bv.y += w.y * vb; Bv.z += w.z * vb; Bv.w += w.w * vb;
        }
        #pragma unroll
        for (int k4 = 0; k4 < 8; k4++) {
            float4 ha = *(const float4*)&h0a[4 * k4];
            float4 hb = *(const float4*)&h0b[4 * k4];
            const float* hap = (const float*)&ha;
            const float* hbp = (const float*)&hb;
            #pragma unroll
            for (int kk = 0; kk < 4; kk++) {
                float4 w = *(const float4*)&sWhh0[(4 * k4 + kk) * 128 + 4 * j];
                float va = hap[kk], vb = hbp[kk];
                A.x  += w.x * va; A.y  += w.y * va; A.z  += w.z * va; A.w  += w.w * va;
                Bv.x += w.x * vb; Bv.y += w.y * vb; Bv.z += w.z * vb; Bv.w += w.w * vb;
            }
        }
        // activations layer 0
        float h0a_new, h0b_new;
        {
            float ig = sigf(A.x), fg = sigf(A.y), gg = tanh_(A.z), og = sigf(A.w);
            c0a = fg * c0a + ig * gg;
            h0a_new = og * tanh_(c0a);
            float ig2 = sigf(Bv.x), fg2 = sigf(Bv.y), gg2 = tanh_(Bv.z), og2 = sigf(Bv.w);
            c0b = fg2 * c0b + ig2 * gg2;
            h0b_new = og2 * tanh_(c0b);
        }
        __syncwarp();
        h0a[j] = h0a_new; h0b[j] = h0b_new;
        __syncwarp();

        // ================= Layer 1 =================
        A = b1q; Bv = b1q;
        #pragma unroll
        for (int k4 = 0; k4 < 8; k4++) {
            float4 ha = *(const float4*)&h0a[4 * k4];
            float4 hb = *(const float4*)&h0b[4 * k4];
            const float* hap = (const float*)&ha;
            const float* hbp = (const float*)&hb;
            #pragma unroll
            for (int kk = 0; kk < 4; kk++) {
                float4 w = *(const float4*)&sWih1[(4 * k4 + kk) * 128 + 4 * j];
                float va = hap[kk], vb = hbp[kk];
                A.x  += w.x * va; A.y  += w.y * va; A.z  += w.z * va; A.w  += w.w * va;
                Bv.x += w.x * vb; Bv.y += w.y * vb; Bv.z += w.z * vb; Bv.w += w.w * vb;
            }
        }
        #pragma unroll
        for (int k4 = 0; k4 < 8; k4++) {
            float4 ha = *(const float4*)&h1a[4 * k4];
            float4 hb = *(const float4*)&h1b[4 * k4];
            const float* hap = (const float*)&ha;
            const float* hbp = (const float*)&hb;
            #pragma unroll
            for (int kk = 0; kk < 4; kk++) {
                float4 w = *(const float4*)&sWhh1[(4 * k4 + kk) * 128 + 4 * j];
                float va = hap[kk], vb = hbp[kk];
                A.x  += w.x * va; A.y  += w.y * va; A.z  += w.z * va; A.w  += w.w * va;
                Bv.x += w.x * vb; Bv.y += w.y * vb; Bv.z += w.z * vb; Bv.w += w.w * vb;
            }
        }
        float h1a_new, h1b_new;
        {
            float ig = sigf(A.x), fg = sigf(A.y), gg = tanh_(A.z), og = sigf(A.w);
            c1a = fg * c1a + ig * gg;
            h1a_new = og * tanh_(c1a);
            float ig2 = sigf(Bv.x), fg2 = sigf(Bv.y), gg2 = tanh_(Bv.z), og2 = sigf(Bv.w);
            c1b = fg2 * c1b + ig2 * gg2;
            h1b_new = og2 * tanh_(c1b);
        }
        __syncwarp();
        h1a[j] = h1a_new; h1b[j] = h1b_new;
        __syncwarp();

        h1a_last = h1a_new; h1b_last = h1b_new;

        // rotate prefetched x
        xca[0]=na0.x; xca[1]=na0.y; xca[2]=na1.x; xca[3]=na1.y; xca[4]=na2.x; xca[5]=na2.y;
        xcb[0]=nb0.x; xcb[1]=nb0.y; xcb[2]=nb1.x; xcb[3]=nb1.y; xcb[4]=nb2.x; xcb[5]=nb2.y;
    }

    // ================= final LayerNorm over H=32 =================
    float g = ln_gamma[j];
    float be = ln_beta[j];

    {
        float s = h1a_last;
        #pragma unroll
        for (int o2 = 16; o2 > 0; o2 >>= 1) s += __shfl_xor_sync(0xffffffffu, s, o2);
        float mu = s * (1.0f / 32.0f);
        float dv = h1a_last - mu;
        float q = dv * dv;
        #pragma unroll
        for (int o2 = 16; o2 > 0; o2 >>= 1) q += __shfl_xor_sync(0xffffffffu, q, o2);
        float var = q * (1.0f / 32.0f);
        out[(size_t)ba * 32 + j] = dv * rsqrtf(var + 1e-5f) * g + be;
    }
    {
        float s = h1b_last;
        #pragma unroll
        for (int o2 = 16; o2 > 0; o2 >>= 1) s += __shfl_xor_sync(0xffffffffu, s, o2);
        float mu = s * (1.0f / 32.0f);
        float dv = h1b_last - mu;
        float q = dv * dv;
        #pragma unroll
        for (int o2 = 16; o2 > 0; o2 >>= 1) q += __shfl_xor_sync(0xffffffffu, q, o2);
        float var = q * (1.0f / 32.0f);
        out[(size_t)bb * 32 + j] = dv * rsqrtf(var + 1e-5f) * g + be;
    }
}

extern "C" void kernel_launch(void* const* d_in, const int* in_sizes, int n_in,
                              void* d_out, int out_size)
{
    const float* x      = (const float*)d_in[0];
    const float* W_ih0  = (const float*)d_in[1];
    const float* W_hh0  = (const float*)d_in[2];
    const float* b_ih0  = (const float*)d_in[3];
    const float* b_hh0  = (const float*)d_in[4];
    const float* W_ih1  = (const float*)d_in[5];
    const float* W_hh1  = (const float*)d_in[6];
    const float* b_ih1  = (const float*)d_in[7];
    const float* b_hh1  = (const float*)d_in[8];
    const float* ln_g   = (const float*)d_in[9];
    const float* ln_b   = (const float*)d_in[10];
    float* out = (float*)d_out;

    cudaFuncSetAttribute(lstm_enc_kernel,
                         cudaFuncAttributeMaxDynamicSharedMemorySize, SMEM_BYTES);
    lstm_enc_kernel<<<NUM_CTAS, CTA_THREADS, SMEM_BYTES>>>(
        x, W_ih0, W_hh0, b_ih0, b_hh0, W_ih1, W_hh1, b_ih1, b_hh1,
        ln_g, ln_b, out);
}

// round 2
// speedup vs baseline: 1.4378x; 1.4378x over previous
#include <cuda_runtime.h>
#include <cuda_bf16.h>

// 2-layer LSTM (H=32) + LayerNorm. B=4096, T=512, D=6.
// Round 2: 4 batches/warp (amortize shared weight reads) + fma.rn.f32x2
// k-pair packing (halve FMA instructions). Lane j owns hidden unit j.
// Weights in shared laid out as (w[2k][g0], w[2k+1][g0], w[2k][g1], w[2k+1][g1])
// so one LDS.128 feeds two FFMA2 b-operands; h broadcast LDS.128 feeds two
// a-operands ((h0,h1),(h2,h3)) with no repacking.

#define T_STEPS 512
#define D_IN 6
#define HID 32
#define BATCH 4096
#define WARPS_PER_CTA 7
#define CTA_THREADS (WARPS_PER_CTA * 32)
#define NUM_CTAS 147            // 147*7 = 1029 warp tasks >= 1024 (4 batch/warp)
#define BPW 4                   // batches per warp

// shared floats:
//  Wih0 if/go: 3kp*32*4 *2 = 768
//  Whh0,Wih1,Whh1 if/go: 16kp*32*4*2 = 4096 each -> 12288
//  hbuf: 7 warps * (4 batches * 64 (h0[32]+h1[32])) = 1792
#define SMEM_FLOATS (768 + 4096*3 + 7*256)
#define SMEM_BYTES (SMEM_FLOATS * 4)

__device__ __forceinline__ unsigned long long pk2(float lo, float hi) {
    unsigned long long r;
    asm("mov.b64 %0, {%1,%2};" : "=l"(r)
        : "r"(__float_as_uint(lo)), "r"(__float_as_uint(hi)));
    return r;
}
__device__ __forceinline__ float2 upk2(unsigned long long v) {
    unsigned int lo, hi;
    asm("mov.b64 {%0,%1}, %2;" : "=r"(lo), "=r"(hi) : "l"(v));
    return make_float2(__uint_as_float(lo), __uint_as_float(hi));
}
__device__ __forceinline__ unsigned long long ffma2(
    unsigned long long a, unsigned long long b, unsigned long long c) {
    unsigned long long d;
    asm("fma.rn.f32x2 %0, %1, %2, %3;" : "=l"(d) : "l"(a), "l"(b), "l"(c));
    return d;
}

__device__ __forceinline__ float sigf(float x) {
    return __fdividef(1.0f, 1.0f + __expf(-x));
}
__device__ __forceinline__ float tanh_(float x) {
    return __fdividef(2.0f, 1.0f + __expf(-2.0f * x)) - 1.0f;
}

__global__ __launch_bounds__(CTA_THREADS, 1)
void lstm_enc_kernel(const float* __restrict__ x,
                     const float* __restrict__ W_ih0,
                     const float* __restrict__ W_hh0,
                     const float* __restrict__ b_ih0,
                     const float* __restrict__ b_hh0,
                     const float* __restrict__ W_ih1,
                     const float* __restrict__ W_hh1,
                     const float* __restrict__ b_ih1,
                     const float* __restrict__ b_hh1,
                     const float* __restrict__ ln_gamma,
                     const float* __restrict__ ln_beta,
                     float* __restrict__ out)
{
    extern __shared__ float smem[];
    float* sIh0 = smem;                 // [3kp][32j][4]  (if | go interleaved? no: two blocks)
    float* sIh0go = sIh0 + 384;
    float* sHh0 = sIh0go + 384;         // if block [16][32][4]
    float* sHh0go = sHh0 + 2048;
    float* sIh1 = sHh0go + 2048;
    float* sIh1go = sIh1 + 2048;
    float* sHh1 = sIh1go + 2048;
    float* sHh1go = sHh1 + 2048;
    float* hbuf = sHh1go + 2048;        // per warp 256 floats: h0[4][32], h1[4][32]

    const int tid = threadIdx.x;

    // ---- stage weights: entry (kp*32+j)*4 = {W[g0*32+j][2kp], W[g0*32+j][2kp+1],
    //                                          W[g1*32+j][2kp], W[g1*32+j][2kp+1]}
    // K=32 matrices (Whh0, Wih1, Whh1): 512 float4-entries per half
    for (int i = tid; i < 512; i += CTA_THREADS) {
        int kp = i >> 5, j = i & 31;
        int k0 = 2 * kp, k1 = 2 * kp + 1;
        float4* d0 = (float4*)sHh0;   float4* d0g = (float4*)sHh0go;
        float4* d1 = (float4*)sIh1;   float4* d1g = (float4*)sIh1go;
        float4* d2 = (float4*)sHh1;   float4* d2g = (float4*)sHh1go;
        d0[i]  = make_float4(W_hh0[(j)*32+k0],    W_hh0[(j)*32+k1],
                             W_hh0[(32+j)*32+k0], W_hh0[(32+j)*32+k1]);
        d0g[i] = make_float4(W_hh0[(64+j)*32+k0], W_hh0[(64+j)*32+k1],
                             W_hh0[(96+j)*32+k0], W_hh0[(96+j)*32+k1]);
        d1[i]  = make_float4(W_ih1[(j)*32+k0],    W_ih1[(j)*32+k1],
                             W_ih1[(32+j)*32+k0], W_ih1[(32+j)*32+k1]);
        d1g[i] = make_float4(W_ih1[(64+j)*32+k0], W_ih1[(64+j)*32+k1],
                             W_ih1[(96+j)*32+k0], W_ih1[(96+j)*32+k1]);
        d2[i]  = make_float4(W_hh1[(j)*32+k0],    W_hh1[(j)*32+k1],
                             W_hh1[(32+j)*32+k0], W_hh1[(32+j)*32+k1]);
        d2g[i] = make_float4(W_hh1[(64+j)*32+k0], W_hh1[(64+j)*32+k1],
                             W_hh1[(96+j)*32+k0], W_hh1[(96+j)*32+k1]);
    }
    // Wih0: K=6 -> 3 kp
    for (int i = tid; i < 96; i += CTA_THREADS) {
        int kp = i >> 5, j = i & 31;
        int k0 = 2 * kp, k1 = 2 * kp + 1;
        ((float4*)sIh0)[i]   = make_float4(W_ih0[(j)*6+k0],    W_ih0[(j)*6+k1],
                                           W_ih0[(32+j)*6+k0], W_ih0[(32+j)*6+k1]);
        ((float4*)sIh0go)[i] = make_float4(W_ih0[(64+j)*6+k0], W_ih0[(64+j)*6+k1],
                                           W_ih0[(96+j)*6+k0], W_ih0[(96+j)*6+k1]);
    }
    __syncthreads();

    const int wid = tid >> 5;
    const int j = tid & 31;
    const int task = blockIdx.x * WARPS_PER_CTA + wid;
    if (task * BPW >= BATCH) return;

    const int b0 = task * BPW;

    float* h0p = hbuf + wid * 256;        // [4][32]
    float* h1p = h0p + 128;               // [4][32]
    #pragma unroll
    for (int q = 0; q < BPW; q++) { h0p[q*32 + j] = 0.0f; h1p[q*32 + j] = 0.0f; }
    __syncwarp();

    // biases per lane
    float bi0 = b_ih0[j]      + b_hh0[j];
    float bf0 = b_ih0[32+j]   + b_hh0[32+j];
    float bg0 = b_ih0[64+j]   + b_hh0[64+j];
    float bo0 = b_ih0[96+j]   + b_hh0[96+j];
    float bi1 = b_ih1[j]      + b_hh1[j];
    float bf1 = b_ih1[32+j]   + b_hh1[32+j];
    float bg1 = b_ih1[64+j]   + b_hh1[64+j];
    float bo1 = b_ih1[96+j]   + b_hh1[96+j];

    float c0[BPW] = {0,0,0,0}, c1[BPW] = {0,0,0,0};
    float h1last[BPW] = {0,0,0,0};

    const float* xp[BPW];
    #pragma unroll
    for (int q = 0; q < BPW; q++) xp[q] = x + (size_t)(b0 + q) * T_STEPS * D_IN;

    // packed x pairs for current step
    unsigned long long xq[BPW][3];
    #pragma unroll
    for (int q = 0; q < BPW; q++) {
        float2 a = *(const float2*)(xp[q] + 0);
        float2 b = *(const float2*)(xp[q] + 2);
        float2 c = *(const float2*)(xp[q] + 4);
        xq[q][0] = pk2(a.x, a.y); xq[q][1] = pk2(b.x, b.y); xq[q][2] = pk2(c.x, c.y);
    }

    const ulonglong2* Wih0if = (const ulonglong2*)sIh0;
    const ulonglong2* Wih0go = (const ulonglong2*)sIh0go;
    const ulonglong2* Whh0if = (const ulonglong2*)sHh0;
    const ulonglong2* Whh0go = (const ulonglong2*)sHh0go;
    const ulonglong2* Wih1if = (const ulonglong2*)sIh1;
    const ulonglong2* Wih1go = (const ulonglong2*)sIh1go;
    const ulonglong2* Whh1if = (const ulonglong2*)sHh1;
    const ulonglong2* Whh1go = (const ulonglong2*)sHh1go;

    for (int t = 0; t < T_STEPS; t++) {
        // prefetch next x
        int tn = (t + 1 < T_STEPS) ? (t + 1) : t;
        float2 nx[BPW][3];
        #pragma unroll
        for (int q = 0; q < BPW; q++) {
            nx[q][0] = *(const float2*)(xp[q] + tn*D_IN + 0);
            nx[q][1] = *(const float2*)(xp[q] + tn*D_IN + 2);
            nx[q][2] = *(const float2*)(xp[q] + tn*D_IN + 4);
        }

        unsigned long long ai[BPW], af[BPW], ag[BPW], ao[BPW];
        #pragma unroll
        for (int q = 0; q < BPW; q++) { ai[q]=0ull; af[q]=0ull; ag[q]=0ull; ao[q]=0ull; }

        // ========== Layer 0 ==========
        // x part (3 kp)
        #pragma unroll
        for (int kp = 0; kp < 3; kp++) {
            ulonglong2 wif = Wih0if[kp*32 + j];
            ulonglong2 wgo = Wih0go[kp*32 + j];
            #pragma unroll
            for (int q = 0; q < BPW; q++) {
                unsigned long long a = xq[q][kp];
                ai[q] = ffma2(a, wif.x, ai[q]);
                af[q] = ffma2(a, wif.y, af[q]);
                ag[q] = ffma2(a, wgo.x, ag[q]);
                ao[q] = ffma2(a, wgo.y, ao[q]);
            }
        }
        // h part (16 kp)
        #pragma unroll
        for (int m = 0; m < 8; m++) {
            ulonglong2 h[BPW];
            #pragma unroll
            for (int q = 0; q < BPW; q++)
                h[q] = ((const ulonglong2*)(h0p + q*32))[m];
            #pragma unroll
            for (int s = 0; s < 2; s++) {
                int kp = 2*m + s;
                ulonglong2 wif = Whh0if[kp*32 + j];
                ulonglong2 wgo = Whh0go[kp*32 + j];
                #pragma unroll
                for (int q = 0; q < BPW; q++) {
                    unsigned long long a = s ? h[q].y : h[q].x;
                    ai[q] = ffma2(a, wif.x, ai[q]);
                    af[q] = ffma2(a, wif.y, af[q]);
                    ag[q] = ffma2(a, wgo.x, ag[q]);
                    ao[q] = ffma2(a, wgo.y, ao[q]);
                }
            }
        }
        // activations L0
        float h0new[BPW];
        #pragma unroll
        for (int q = 0; q < BPW; q++) {
            float2 ui = upk2(ai[q]), uf = upk2(af[q]), ug = upk2(ag[q]), uo = upk2(ao[q]);
            float gi = sigf(bi0 + ui.x + ui.y);
            float gf = sigf(bf0 + uf.x + uf.y);
            float gg = tanh_(bg0 + ug.x + ug.y);
            float go = sigf(bo0 + uo.x + uo.y);
            c0[q] = gf * c0[q] + gi * gg;
            h0new[q] = go * tanh_(c0[q]);
        }
        __syncwarp();
        #pragma unroll
        for (int q = 0; q < BPW; q++) h0p[q*32 + j] = h0new[q];
        __syncwarp();

        // ========== Layer 1 ==========
        #pragma unroll
        for (int q = 0; q < BPW; q++) { ai[q]=0ull; af[q]=0ull; ag[q]=0ull; ao[q]=0ull; }

        #pragma unroll
        for (int m = 0; m < 8; m++) {
            ulonglong2 h[BPW];
            #pragma unroll
            for (int q = 0; q < BPW; q++)
                h[q] = ((const ulonglong2*)(h0p + q*32))[m];
            #pragma unroll
            for (int s = 0; s < 2; s++) {
                int kp = 2*m + s;
                ulonglong2 wif = Wih1if[kp*32 + j];
                ulonglong2 wgo = Wih1go[kp*32 + j];
                #pragma unroll
                for (int q = 0; q < BPW; q++) {
                    unsigned long long a = s ? h[q].y : h[q].x;
                    ai[q] = ffma2(a, wif.x, ai[q]);
                    af[q] = ffma2(a, wif.y, af[q]);
                    ag[q] = ffma2(a, wgo.x, ag[q]);
                    ao[q] = ffma2(a, wgo.y, ao[q]);
                }
            }
        }
        #pragma unroll
        for (int m = 0; m < 8; m++) {
            ulonglong2 h[BPW];
            #pragma unroll
            for (int q = 0; q < BPW; q++)
                h[q] = ((const ulonglong2*)(h1p + q*32))[m];
            #pragma unroll
            for (int s = 0; s < 2; s++) {
                int kp = 2*m + s;
                ulonglong2 wif = Whh1if[kp*32 + j];
                ulonglong2 wgo = Whh1go[kp*32 + j];
                #pragma unroll
                for (int q = 0; q < BPW; q++) {
                    unsigned long long a = s ? h[q].y : h[q].x;
                    ai[q] = ffma2(a, wif.x, ai[q]);
                    af[q] = ffma2(a, wif.y, af[q]);
                    ag[q] = ffma2(a, wgo.x, ag[q]);
                    ao[q] = ffma2(a, wgo.y, ao[q]);
                }
            }
        }
        float h1new[BPW];
        #pragma unroll
        for (int q = 0; q < BPW; q++) {
            float2 ui = upk2(ai[q]), uf = upk2(af[q]), ug = upk2(ag[q]), uo = upk2(ao[q]);
            float gi = sigf(bi1 + ui.x + ui.y);
            float gf = sigf(bf1 + uf.x + uf.y);
            float gg = tanh_(bg1 + ug.x + ug.y);
            float go = sigf(bo1 + uo.x + uo.y);
            c1[q] = gf * c1[q] + gi * gg;
            h1new[q] = go * tanh_(c1[q]);
            h1last[q] = h1new[q];
        }
        __syncwarp();
        #pragma unroll
        for (int q = 0; q < BPW; q++) h1p[q*32 + j] = h1new[q];
        __syncwarp();

        // rotate x prefetch
        #pragma unroll
        for (int q = 0; q < BPW; q++) {
            xq[q][0] = pk2(nx[q][0].x, nx[q][0].y);
            xq[q][1] = pk2(nx[q][1].x, nx[q][1].y);
            xq[q][2] = pk2(nx[q][2].x, nx[q][2].y);
        }
    }

    // ========== final LayerNorm over H=32 ==========
    float g = ln_gamma[j];
    float be = ln_beta[j];
    #pragma unroll
    for (int q = 0; q < BPW; q++) {
        float v = h1last[q];
        float s = v;
        #pragma unroll
        for (int o2 = 16; o2 > 0; o2 >>= 1) s += __shfl_xor_sync(0xffffffffu, s, o2);
        float mu = s * (1.0f / 32.0f);
        float dv = v - mu;
        float qq = dv * dv;
        #pragma unroll
        for (int o2 = 16; o2 > 0; o2 >>= 1) qq += __shfl_xor_sync(0xffffffffu, qq, o2);
        float var = qq * (1.0f / 32.0f);
        out[(size_t)(b0 + q) * 32 + j] = dv * rsqrtf(var + 1e-5f) * g + be;
    }
}

extern "C" void kernel_launch(void* const* d_in, const int* in_sizes, int n_in,
                              void* d_out, int out_size)
{
    const float* x      = (const float*)d_in[0];
    const float* W_ih0  = (const float*)d_in[1];
    const float* W_hh0  = (const float*)d_in[2];
    const float* b_ih0  = (const float*)d_in[3];
    const float* b_hh0  = (const float*)d_in[4];
    const float* W_ih1  = (const float*)d_in[5];
    const float* W_hh1  = (const float*)d_in[6];
    const float* b_ih1  = (const float*)d_in[7];
    const float* b_hh1  = (const float*)d_in[8];
    const float* ln_g   = (const float*)d_in[9];
    const float* ln_b   = (const float*)d_in[10];
    float* out = (float*)d_out;

    cudaFuncSetAttribute(lstm_enc_kernel,
                         cudaFuncAttributeMaxDynamicSharedMemorySize, SMEM_BYTES);
    lstm_enc_kernel<<<NUM_CTAS, CTA_THREADS, SMEM_BYTES>>>(
        x, W_ih0, W_hh0, b_ih0, b_hh0, W_ih1, W_hh1, b_ih1, b_hh1,
        ln_g, ln_b, out);
}